// round 1
// baseline (speedup 1.0000x reference)
#include <cuda_runtime.h>

#define B_  32
#define T_  12
#define N_  1024
#define F_  64
#define O_  64
#define TO_ 768   // T_*O_

typedef unsigned long long ull;

// Scratch (device globals: allocation-free rule)
__device__ float g_R2[B_ * N_ * TO_];  // x @ Theta2          (layout [B][N][T*O])
__device__ float g_Z [B_ * N_ * TO_];  // x @ Theta1, then Z
__device__ float g_D [B_ * N_ * TO_];  // x @ (Theta0-Theta2)
__device__ float g_lam[B_];

// packed f32x2 FMA: d = a*b + d (per 32-bit half)
#define FMA2(d, a, b) asm volatile("fma.rn.f32x2 %0, %1, %2, %0;" : "+l"(d) : "l"(a), "l"(b))

__global__ void lam_init_kernel() {
    if (threadIdx.x < B_) g_lam[threadIdx.x] = 1.0f;  // clamp floor
}

// One block per (b, n) row: sum A[b,n,:], atomicMax into g_lam[b]
__global__ __launch_bounds__(128) void rowsum_max_kernel(const float* __restrict__ A) {
    __shared__ float red[128];
    int row = blockIdx.x;            // b*N + n
    int b = row >> 10;
    const float* ap = A + (size_t)row * N_;
    float s = 0.f;
    for (int m = threadIdx.x; m < N_; m += 128) s += ap[m];
    red[threadIdx.x] = s;
    __syncthreads();
    for (int off = 64; off > 0; off >>= 1) {
        if (threadIdx.x < off) red[threadIdx.x] += red[threadIdx.x + off];
        __syncthreads();
    }
    if (threadIdx.x == 0)
        atomicMax((int*)&g_lam[b], __float_as_int(red[0]));  // positive floats: int order OK
}

// Feature transform: for 64 rows (b,t,n) per block compute
//   D = x@(Th0-Th2), R1 = x@Th1, R2 = x@Th2, stored in [B][N][T*O] layout.
__global__ __launch_bounds__(256) void feat_kernel(const float* __restrict__ x,
                                                   const float* __restrict__ Th) {
    __shared__ float ThC[32 * 192];   // f-chunk x 192 combined output cols
    __shared__ float xs[64][65];
    int tid = threadIdx.x;
    int base = blockIdx.x * 64;

    for (int i = tid; i < 64 * 64; i += 256) {
        int r = i >> 6, f = i & 63;
        xs[r][f] = x[(size_t)(base + r) * 64 + f];
    }

    int row = tid >> 2, lane4 = tid & 3;
    float acc[48];
#pragma unroll
    for (int j = 0; j < 48; j++) acc[j] = 0.f;

    for (int fc = 0; fc < 2; fc++) {
        __syncthreads();
        for (int i = tid; i < 32 * 192; i += 256) {
            int f = fc * 32 + (i / 192), c = i % 192;
            int k = c >> 6, o = c & 63;
            float v;
            if (k == 0) v = Th[f * 64 + o] - Th[2 * 4096 + f * 64 + o];
            else        v = Th[k * 4096 + f * 64 + o];
            ThC[i] = v;
        }
        __syncthreads();
#pragma unroll 4
        for (int ff = 0; ff < 32; ff++) {
            float xv = xs[row][fc * 32 + ff];
            const float4* th4 = (const float4*)&ThC[ff * 192];
#pragma unroll
            for (int q = 0; q < 12; q++) {
                float4 t = th4[lane4 + 4 * q];
                acc[4 * q + 0] += xv * t.x;
                acc[4 * q + 1] += xv * t.y;
                acc[4 * q + 2] += xv * t.z;
                acc[4 * q + 3] += xv * t.w;
            }
        }
    }

    int r = base + row;
    int b = r / (T_ * N_);
    int rem = r - b * (T_ * N_);
    int t = rem >> 10;
    int n = rem & 1023;
    size_t obase = ((size_t)(b * N_ + n) * T_ + t) * 64;
#pragma unroll
    for (int q = 0; q < 12; q++) {
        int c = 4 * (lane4 + 4 * q);
        int k = c >> 6, o = c & 63;
        float* dst = (k == 0) ? g_D : ((k == 1) ? g_Z : g_R2);
        float4 v = make_float4(acc[4 * q + 0], acc[4 * q + 1], acc[4 * q + 2], acc[4 * q + 3]);
        *(float4*)&dst[obase + o] = v;
    }
}

// Batched GEMM: acc = A[b] (1024x1024) @ Bsrc[b] (1024x768), tile 128x64, BK=32.
// MODE 1: Z  = R1 + (4/lam)*acc - 2*R2          (acc = A@R2, write into g_Z)
// MODE 2: out = relu(D + (2/lam)*acc - Z)       (acc = A@Z, write d_out [B,T,N,O])
template <int MODE>
__global__ __launch_bounds__(256) void gemm_kernel(const float* __restrict__ A,
                                                   float* __restrict__ out) {
    __shared__ float As[32][132];     // transposed A tile [k][m], padded
    __shared__ float Bs2[32][128];    // B tile with each value duplicated pairwise
    int b   = blockIdx.z;
    int bm0 = blockIdx.y * 128;
    int bn0 = blockIdx.x * 64;
    int tid = threadIdx.x;
    int tx = tid & 15, ty = tid >> 4;            // 16x16 threads; 8x4 outputs each
    const float* Ab = A + (size_t)b * N_ * N_;
    const float* Bsrc = (MODE == 1) ? g_R2 : g_Z;

    ull acc[16];
#pragma unroll
    for (int i = 0; i < 16; i++) acc[i] = 0ull;

    for (int kt = 0; kt < N_; kt += 32) {
        // A tile: 128 rows x 32 k, float4 loads, store transposed
#pragma unroll
        for (int l = 0; l < 4; l++) {
            int idx = tid + l * 256;            // 0..1023
            int row = idx >> 3, c4 = idx & 7;
            float4 v = *(const float4*)&Ab[(size_t)(bm0 + row) * N_ + kt + 4 * c4];
            As[4 * c4 + 0][row] = v.x;
            As[4 * c4 + 1][row] = v.y;
            As[4 * c4 + 2][row] = v.z;
            As[4 * c4 + 3][row] = v.w;
        }
        // B tile: 32 k x 64 cols, duplicated pairwise for f32x2
#pragma unroll
        for (int l = 0; l < 8; l++) {
            int idx = tid + l * 256;            // 0..2047
            int m = idx >> 6, c = idx & 63;
            float v = Bsrc[(size_t)(b * N_ + kt + m) * TO_ + bn0 + c];
            Bs2[m][2 * c]     = v;
            Bs2[m][2 * c + 1] = v;
        }
        __syncthreads();
#pragma unroll 8
        for (int k = 0; k < 32; k++) {
            ulonglong2 aA = *(const ulonglong2*)&As[k][ty * 8];       // rows (0,1),(2,3)
            ulonglong2 aB = *(const ulonglong2*)&As[k][ty * 8 + 4];   // rows (4,5),(6,7)
            ulonglong2 b01 = *(const ulonglong2*)&Bs2[k][8 * tx];     // dup(c0),dup(c1)
            ulonglong2 b23 = *(const ulonglong2*)&Bs2[k][8 * tx + 4]; // dup(c2),dup(c3)
            ull ap0 = aA.x, ap1 = aA.y, ap2 = aB.x, ap3 = aB.y;
            FMA2(acc[ 0], ap0, b01.x); FMA2(acc[ 1], ap0, b01.y);
            FMA2(acc[ 2], ap0, b23.x); FMA2(acc[ 3], ap0, b23.y);
            FMA2(acc[ 4], ap1, b01.x); FMA2(acc[ 5], ap1, b01.y);
            FMA2(acc[ 6], ap1, b23.x); FMA2(acc[ 7], ap1, b23.y);
            FMA2(acc[ 8], ap2, b01.x); FMA2(acc[ 9], ap2, b01.y);
            FMA2(acc[10], ap2, b23.x); FMA2(acc[11], ap2, b23.y);
            FMA2(acc[12], ap3, b01.x); FMA2(acc[13], ap3, b01.y);
            FMA2(acc[14], ap3, b23.x); FMA2(acc[15], ap3, b23.y);
        }
        __syncthreads();
    }

    // unpack: acc[ip*4+j] = (row 2ip, row 2ip+1) for col j
    float cf[8][4];
#pragma unroll
    for (int ip = 0; ip < 4; ip++)
#pragma unroll
        for (int j = 0; j < 4; j++) {
            ull v = acc[ip * 4 + j];
            cf[2 * ip + 0][j] = __uint_as_float((unsigned)v);
            cf[2 * ip + 1][j] = __uint_as_float((unsigned)(v >> 32));
        }

    float lam = g_lam[b];
    if (MODE == 1) {
        float s = 4.0f / lam;
#pragma unroll
        for (int r = 0; r < 8; r++) {
            int n = bm0 + ty * 8 + r;
            size_t idx = (size_t)(b * N_ + n) * TO_ + bn0 + tx * 4;
            float4 r1 = *(const float4*)&g_Z[idx];
            float4 r2 = *(const float4*)&g_R2[idx];
            float4 z;
            z.x = r1.x + s * cf[r][0] - 2.f * r2.x;
            z.y = r1.y + s * cf[r][1] - 2.f * r2.y;
            z.z = r1.z + s * cf[r][2] - 2.f * r2.z;
            z.w = r1.w + s * cf[r][3] - 2.f * r2.w;
            *(float4*)&g_Z[idx] = z;
        }
    } else {
        float s = 2.0f / lam;
        int t = blockIdx.x;   // bn0/64: each col-tile is exactly one timestep
#pragma unroll
        for (int r = 0; r < 8; r++) {
            int n = bm0 + ty * 8 + r;
            size_t idx = (size_t)(b * N_ + n) * TO_ + bn0 + tx * 4;
            float4 dv = *(const float4*)&g_D[idx];
            float4 zv = *(const float4*)&g_Z[idx];
            float4 o;
            o.x = fmaxf(dv.x + s * cf[r][0] - zv.x, 0.f);
            o.y = fmaxf(dv.y + s * cf[r][1] - zv.y, 0.f);
            o.z = fmaxf(dv.z + s * cf[r][2] - zv.z, 0.f);
            o.w = fmaxf(dv.w + s * cf[r][3] - zv.w, 0.f);
            size_t oidx = ((size_t)(b * T_ + t) * N_ + n) * 64 + tx * 4;
            *(float4*)&out[oidx] = o;
        }
    }
}

extern "C" void kernel_launch(void* const* d_in, const int* in_sizes, int n_in,
                              void* d_out, int out_size) {
    // Identify inputs by element count (robust to metadata order)
    const float* x = nullptr;      // 32*12*1024*64 = 25165824
    const float* A = nullptr;      // 32*1024*1024  = 33554432
    const float* Th = nullptr;     // 3*64*64       = 12288
    for (int i = 0; i < n_in; i++) {
        if (in_sizes[i] == B_ * N_ * N_)           A  = (const float*)d_in[i];
        else if (in_sizes[i] == B_ * T_ * N_ * F_) x  = (const float*)d_in[i];
        else if (in_sizes[i] == 3 * F_ * O_)       Th = (const float*)d_in[i];
    }
    float* out = (float*)d_out;

    lam_init_kernel<<<1, 32>>>();
    rowsum_max_kernel<<<B_ * N_, 128>>>(A);
    feat_kernel<<<(B_ * T_ * N_) / 64, 256>>>(x, Th);
    dim3 gg(TO_ / 64, N_ / 128, B_);
    gemm_kernel<1><<<gg, 256>>>(A, out);
    gemm_kernel<2><<<gg, 256>>>(A, out);
}

// round 3
// speedup vs baseline: 2.4138x; 2.4138x over previous
#include <cuda_runtime.h>
#include <cuda_bf16.h>
#include <cstdint>

#define B_  32
#define T_  12
#define N_  1024
#define F_  64
#define TO_ 768   // T_*O

// ---------------- device scratch (allocation-free rule) ----------------
__device__ __align__(16) __nv_bfloat16 g_Ah[(size_t)B_ * N_ * N_];
__device__ __align__(16) __nv_bfloat16 g_Al[(size_t)B_ * N_ * N_];
__device__ __align__(16) __nv_bfloat16 g_R2h[(size_t)B_ * TO_ * N_];
__device__ __align__(16) __nv_bfloat16 g_R2l[(size_t)B_ * TO_ * N_];
__device__ __align__(16) __nv_bfloat16 g_Zh[(size_t)B_ * TO_ * N_];
__device__ __align__(16) __nv_bfloat16 g_Zl[(size_t)B_ * TO_ * N_];
__device__ __align__(16) float g_R1t[(size_t)B_ * TO_ * N_];
__device__ __align__(16) float g_Dt [(size_t)B_ * TO_ * N_];
__device__ float g_lam[B_];

// ---------------- PTX helpers ----------------
__device__ __forceinline__ uint32_t smem_u32(const void* p) {
    uint32_t a;
    asm("{ .reg .u64 t; cvta.to.shared.u64 t, %1; cvt.u32.u64 %0, t; }" : "=r"(a) : "l"(p));
    return a;
}
#define CP16(dst, src) asm volatile("cp.async.cg.shared.global [%0], [%1], 16;" :: "r"(dst), "l"(src))
#define CP_COMMIT() asm volatile("cp.async.commit_group;" ::: "memory")
#define CP_WAIT(n)  asm volatile("cp.async.wait_group %0;" :: "n"(n) : "memory")

__device__ __forceinline__ void ldsm4(unsigned* r, uint32_t addr) {
    asm volatile("ldmatrix.sync.aligned.m8n8.x4.shared.b16 {%0,%1,%2,%3}, [%4];"
                 : "=r"(r[0]), "=r"(r[1]), "=r"(r[2]), "=r"(r[3]) : "r"(addr));
}
__device__ __forceinline__ void mma16816(float* c, const unsigned* a, const unsigned* b) {
    asm volatile("mma.sync.aligned.m16n8k16.row.col.f32.bf16.bf16.f32 "
                 "{%0,%1,%2,%3}, {%4,%5,%6,%7}, {%8,%9}, {%0,%1,%2,%3};"
                 : "+f"(c[0]), "+f"(c[1]), "+f"(c[2]), "+f"(c[3])
                 : "r"(a[0]), "r"(a[1]), "r"(a[2]), "r"(a[3]), "r"(b[0]), "r"(b[1]));
}

// ---------------- lambda init + rowsum + A split ----------------
__global__ void lam_init_kernel() {
    if (threadIdx.x < B_) g_lam[threadIdx.x] = 1.0f;
}

__global__ __launch_bounds__(256) void rowsum_conv_kernel(const float* __restrict__ A) {
    __shared__ float red[8];
    int row = blockIdx.x;                 // b*1024 + n
    int b = row >> 10;
    int t = threadIdx.x;
    const float4* ap = (const float4*)(A + (size_t)row * N_);
    float4 v = ap[t];
    unsigned h01, h23, l01, l23;
    {
        __nv_bfloat16 h0 = __float2bfloat16(v.x), h1 = __float2bfloat16(v.y);
        __nv_bfloat16 h2 = __float2bfloat16(v.z), h3 = __float2bfloat16(v.w);
        __nv_bfloat16 l0 = __float2bfloat16(v.x - __bfloat162float(h0));
        __nv_bfloat16 l1 = __float2bfloat16(v.y - __bfloat162float(h1));
        __nv_bfloat16 l2 = __float2bfloat16(v.z - __bfloat162float(h2));
        __nv_bfloat16 l3 = __float2bfloat16(v.w - __bfloat162float(h3));
        h01 = ((unsigned)__bfloat16_as_ushort(h1) << 16) | __bfloat16_as_ushort(h0);
        h23 = ((unsigned)__bfloat16_as_ushort(h3) << 16) | __bfloat16_as_ushort(h2);
        l01 = ((unsigned)__bfloat16_as_ushort(l1) << 16) | __bfloat16_as_ushort(l0);
        l23 = ((unsigned)__bfloat16_as_ushort(l3) << 16) | __bfloat16_as_ushort(l2);
    }
    ((uint2*)g_Ah)[(size_t)row * 256 + t] = make_uint2(h01, h23);
    ((uint2*)g_Al)[(size_t)row * 256 + t] = make_uint2(l01, l23);

    float s = v.x + v.y + v.z + v.w;
#pragma unroll
    for (int off = 16; off > 0; off >>= 1) s += __shfl_xor_sync(0xFFFFFFFF, s, off);
    if ((t & 31) == 0) red[t >> 5] = s;
    __syncthreads();
    if (t < 8) {
        float ss = red[t];
#pragma unroll
        for (int off = 4; off > 0; off >>= 1) ss += __shfl_xor_sync(0xFF, ss, off);
        if (t == 0) atomicMax((int*)&g_lam[b], __float_as_int(ss));
    }
}

// ---------------- feature transform: D=x@(Th0-Th2), R1=x@Th1, R2=x@Th2 ----------------
// outputs transposed: g_Dt/g_R1t fp32 [b][to][n]; g_R2h/g_R2l bf16 split [b][to][n]
__global__ __launch_bounds__(256) void feat_kernel(const float* __restrict__ x,
                                                   const float* __restrict__ Th) {
    __shared__ float ThC[32 * 192];
    __shared__ float xsT[64 * 65];
    int tid = threadIdx.x;
    int base = blockIdx.x * 64;

    for (int i = tid; i < 64 * 64; i += 256) {
        int r = i >> 6, f = i & 63;
        xsT[r * 65 + f] = x[(size_t)(base + r) * 64 + f];
    }

    int row = tid >> 2, lane4 = tid & 3;
    float acc[48];
#pragma unroll
    for (int j = 0; j < 48; j++) acc[j] = 0.f;

    for (int fc = 0; fc < 2; fc++) {
        __syncthreads();
        for (int i = tid; i < 32 * 192; i += 256) {
            int f = fc * 32 + (i / 192), c = i % 192;
            int k = c >> 6, o = c & 63;
            float v;
            if (k == 0) v = Th[f * 64 + o] - Th[2 * 4096 + f * 64 + o];
            else        v = Th[k * 4096 + f * 64 + o];
            ThC[i] = v;
        }
        __syncthreads();
#pragma unroll 4
        for (int ff = 0; ff < 32; ff++) {
            float xv = xsT[row * 65 + fc * 32 + ff];
            const float4* th4 = (const float4*)&ThC[ff * 192];
#pragma unroll
            for (int q = 0; q < 12; q++) {
                float4 tv = th4[lane4 + 4 * q];
                acc[4 * q + 0] += xv * tv.x;
                acc[4 * q + 1] += xv * tv.y;
                acc[4 * q + 2] += xv * tv.z;
                acc[4 * q + 3] += xv * tv.w;
            }
        }
    }

    int b = base / (T_ * N_);
    int rem = base - b * (T_ * N_);
    int tt = rem >> 10;
    int nbase = rem & 1023;
    int o = tid >> 2, seg = tid & 3;

    for (int kg = 0; kg < 3; kg++) {
        __syncthreads();
#pragma unroll
        for (int q2 = 0; q2 < 4; q2++)
#pragma unroll
            for (int j = 0; j < 4; j++) {
                int cl = 16 * q2 + 4 * lane4 + j;
                xsT[cl * 65 + row] = acc[4 * (kg * 4 + q2) + j];
            }
        __syncthreads();
        size_t rb = ((size_t)b * TO_ + tt * 64 + o) * N_ + nbase + seg * 16;
        const float* src = &xsT[o * 65 + seg * 16];
        if (kg < 2) {
            float* dst = (kg == 0) ? g_Dt : g_R1t;
#pragma unroll
            for (int u = 0; u < 4; u++) {
                float4 v = make_float4(src[4 * u], src[4 * u + 1], src[4 * u + 2], src[4 * u + 3]);
                *(float4*)&dst[rb + 4 * u] = v;
            }
        } else {
            unsigned hh[8], ll[8];
#pragma unroll
            for (int p = 0; p < 8; p++) {
                float f0 = src[2 * p], f1 = src[2 * p + 1];
                __nv_bfloat16 h0 = __float2bfloat16(f0), h1 = __float2bfloat16(f1);
                __nv_bfloat16 q0 = __float2bfloat16(f0 - __bfloat162float(h0));
                __nv_bfloat16 q1 = __float2bfloat16(f1 - __bfloat162float(h1));
                hh[p] = ((unsigned)__bfloat16_as_ushort(h1) << 16) | __bfloat16_as_ushort(h0);
                ll[p] = ((unsigned)__bfloat16_as_ushort(q1) << 16) | __bfloat16_as_ushort(q0);
            }
            *(uint4*)&g_R2h[rb]     = make_uint4(hh[0], hh[1], hh[2], hh[3]);
            *(uint4*)&g_R2h[rb + 8] = make_uint4(hh[4], hh[5], hh[6], hh[7]);
            *(uint4*)&g_R2l[rb]     = make_uint4(ll[0], ll[1], ll[2], ll[3]);
            *(uint4*)&g_R2l[rb + 8] = make_uint4(ll[4], ll[5], ll[6], ll[7]);
        }
    }
}

// ---------------- HMMA GEMM: C[128x128] = A[b] @ Bsrc[b], split-bf16 x3 ----------------
// MODE 1: Bsrc = R2;  epilogue Z = R1 + (4/lam)C - 2*R2  -> g_Zh/g_Zl (bf16 split)
// MODE 2: Bsrc = Z;   epilogue out = relu(D + (2/lam)C - Z) -> d_out [B,T,N,O]
#define STAGE_BYTES 65536
#define GEMM_SMEM   (3 * STAGE_BYTES)

__device__ __forceinline__ void fill_stage(uint32_t st, int kt, int bm0, int bn0,
                                           const __nv_bfloat16* __restrict__ Ah,
                                           const __nv_bfloat16* __restrict__ Al,
                                           const __nv_bfloat16* __restrict__ Bh,
                                           const __nv_bfloat16* __restrict__ Bl, int tid) {
    int ch = tid & 7, r0 = tid >> 3;  // 8 x 16B chunks per 128B row; r0 = 0..31
#pragma unroll
    for (int i = 0; i < 4; i++) {
        int row = r0 + 32 * i;
        uint32_t sw = (uint32_t)(row * 128 + ((ch ^ (row & 7)) << 4));
        size_t ao = (size_t)(bm0 + row) * N_ + kt + ch * 8;
        size_t bo = (size_t)(bn0 + row) * N_ + kt + ch * 8;
        CP16(st + sw,         Ah + ao);
        CP16(st + 16384 + sw, Al + ao);
        CP16(st + 32768 + sw, Bh + bo);
        CP16(st + 49152 + sw, Bl + bo);
    }
}

template <int MODE>
__global__ __launch_bounds__(256) void gemm_hmma(float* __restrict__ out) {
    extern __shared__ __align__(1024) char smem[];
    uint32_t sb = smem_u32(smem);
    int tid = threadIdx.x, lane = tid & 31, wid = tid >> 5;
    int wm = wid & 1, wn = wid >> 1;                 // warp tile: 64 rows x 32 cols
    int b = blockIdx.z, bm0 = blockIdx.y * 128, bn0 = blockIdx.x * 128;

    const __nv_bfloat16* Agh = g_Ah + ((size_t)b << 20);
    const __nv_bfloat16* Agl = g_Al + ((size_t)b << 20);
    const __nv_bfloat16* Bgh = (MODE == 1) ? (g_R2h + (size_t)b * TO_ * N_) : (g_Zh + (size_t)b * TO_ * N_);
    const __nv_bfloat16* Bgl = (MODE == 1) ? (g_R2l + (size_t)b * TO_ * N_) : (g_Zl + (size_t)b * TO_ * N_);

    float acc[4][4][4];
#pragma unroll
    for (int i = 0; i < 4; i++)
#pragma unroll
        for (int j = 0; j < 4; j++)
#pragma unroll
            for (int q = 0; q < 4; q++) acc[i][j][q] = 0.f;

    // ldmatrix lane-address components
    int a_r = (lane & 7) + ((lane >> 3) & 1) * 8;   // row-in-16
    int a_c = lane >> 4;                             // k-chunk half
    int b_r = (lane & 7) + (lane >> 4) * 8;
    int b_c = (lane >> 3) & 1;

    // prefill 3 stages (k chunks 0..2)
#pragma unroll
    for (int c = 0; c < 3; c++) {
        fill_stage(sb + c * STAGE_BYTES, c * 64, bm0, bn0, Agh, Agl, Bgh, Bgl, tid);
        CP_COMMIT();
    }

    for (int c = 0; c < 16; c++) {
        uint32_t stage = sb + (c % 3) * STAGE_BYTES;
        if (c <= 13)      CP_WAIT(2);
        else if (c == 14) CP_WAIT(1);
        else              CP_WAIT(0);
        __syncthreads();

#pragma unroll
        for (int kk = 0; kk < 4; kk++) {            // 4 x k16 per stage
            unsigned ah[4][4], al[4][4], bh[2][4], bl[2][4];
#pragma unroll
            for (int i = 0; i < 4; i++) {
                int row = wm * 64 + 16 * i + a_r;
                int chunk = kk * 2 + a_c;
                uint32_t addr = stage + row * 128 + ((chunk ^ (row & 7)) << 4);
                ldsm4(ah[i], addr);
                ldsm4(al[i], addr + 16384);
            }
#pragma unroll
            for (int j2 = 0; j2 < 2; j2++) {
                int row = wn * 32 + 16 * j2 + b_r;
                int chunk = kk * 2 + b_c;
                uint32_t addr = stage + 32768 + row * 128 + ((chunk ^ (row & 7)) << 4);
                ldsm4(bh[j2], addr);
                ldsm4(bl[j2], addr + 16384);
            }
#pragma unroll
            for (int i = 0; i < 4; i++)
#pragma unroll
                for (int j = 0; j < 4; j++) {
                    const unsigned* pbh = &bh[j >> 1][(j & 1) * 2];
                    const unsigned* pbl = &bl[j >> 1][(j & 1) * 2];
                    mma16816(acc[i][j], ah[i], pbh);
                    mma16816(acc[i][j], ah[i], pbl);
                    mma16816(acc[i][j], al[i], pbh);
                }
        }

        if (c + 3 < 16) {
            __syncthreads();
            fill_stage(stage, (c + 3) * 64, bm0, bn0, Agh, Agl, Bgh, Bgl, tid);
            CP_COMMIT();
        }
    }

    // ---------------- epilogue ----------------
    float lam = g_lam[b];
    int m0 = bm0 + wm * 64, to0 = bn0 + wn * 32;
    int rr = lane >> 2, cc = (lane & 3) * 2;

    if (MODE == 1) {
        float s4 = 4.0f / lam;
#pragma unroll
        for (int i = 0; i < 4; i++)
#pragma unroll
            for (int j = 0; j < 4; j++)
#pragma unroll
                for (int h = 0; h < 2; h++) {
                    int n = m0 + 16 * i + rr + 8 * h;
#pragma unroll
                    for (int q = 0; q < 2; q++) {
                        int to = to0 + 8 * j + cc + q;
                        size_t bi = ((size_t)b * TO_ + to) * N_ + n;
                        float r2 = __bfloat162float(g_R2h[bi]) + __bfloat162float(g_R2l[bi]);
                        float z = g_R1t[bi] + s4 * acc[i][j][2 * h + q] - 2.0f * r2;
                        __nv_bfloat16 zh = __float2bfloat16(z);
                        g_Zh[bi] = zh;
                        g_Zl[bi] = __float2bfloat16(z - __bfloat162float(zh));
                    }
                }
    } else {
        float s2 = 2.0f / lam;
        int t = (bn0 + wn * 32) >> 6;
        int o0 = (bn0 + wn * 32) & 63;
#pragma unroll
        for (int i = 0; i < 4; i++)
#pragma unroll
            for (int j = 0; j < 4; j++)
#pragma unroll
                for (int h = 0; h < 2; h++) {
                    int n = m0 + 16 * i + rr + 8 * h;
                    float2 v;
#pragma unroll
                    for (int q = 0; q < 2; q++) {
                        int to = to0 + 8 * j + cc + q;
                        size_t bi = ((size_t)b * TO_ + to) * N_ + n;
                        float z = __bfloat162float(g_Zh[bi]) + __bfloat162float(g_Zl[bi]);
                        float val = g_Dt[bi] + s2 * acc[i][j][2 * h + q] - z;
                        ((float*)&v)[q] = fmaxf(val, 0.f);
                    }
                    size_t oi = ((size_t)(b * T_ + t) * N_ + n) * 64 + o0 + 8 * j + cc;
                    *(float2*)&out[oi] = v;
                }
    }
}

// ---------------- launch ----------------
extern "C" void kernel_launch(void* const* d_in, const int* in_sizes, int n_in,
                              void* d_out, int out_size) {
    const float* x = nullptr;
    const float* A = nullptr;
    const float* Th = nullptr;
    for (int i = 0; i < n_in; i++) {
        if (in_sizes[i] == B_ * N_ * N_)           A  = (const float*)d_in[i];
        else if (in_sizes[i] == B_ * T_ * N_ * F_) x  = (const float*)d_in[i];
        else if (in_sizes[i] == 3 * F_ * 64)       Th = (const float*)d_in[i];
    }
    float* out = (float*)d_out;

    cudaFuncSetAttribute(gemm_hmma<1>, cudaFuncAttributeMaxDynamicSharedMemorySize, GEMM_SMEM);
    cudaFuncSetAttribute(gemm_hmma<2>, cudaFuncAttributeMaxDynamicSharedMemorySize, GEMM_SMEM);

    lam_init_kernel<<<1, 32>>>();
    rowsum_conv_kernel<<<B_ * N_, 256>>>(A);
    feat_kernel<<<(B_ * T_ * N_) / 64, 256>>>(x, Th);
    dim3 gg(TO_ / 128, N_ / 128, B_);
    gemm_hmma<1><<<gg, 256, GEMM_SMEM>>>(out);
    gemm_hmma<2><<<gg, 256, GEMM_SMEM>>>(out);
}

// round 6
// speedup vs baseline: 3.5949x; 1.4893x over previous
#include <cuda_runtime.h>
#include <cuda_bf16.h>
#include <cstdint>

#define B_  32
#define T_  12
#define N_  1024
#define F_  64
#define TO_ 768   // T_*O

// ---------------- device scratch (allocation-free rule) ----------------
__device__ __align__(16) __nv_bfloat16 g_Ah[(size_t)B_ * N_ * N_];
__device__ __align__(16) __nv_bfloat16 g_Al[(size_t)B_ * N_ * N_];
__device__ __align__(16) __nv_bfloat16 g_R2h[(size_t)B_ * TO_ * N_];
__device__ __align__(16) __nv_bfloat16 g_R2l[(size_t)B_ * TO_ * N_];
__device__ __align__(16) __nv_bfloat16 g_Zh[(size_t)B_ * TO_ * N_];
__device__ __align__(16) __nv_bfloat16 g_Zl[(size_t)B_ * TO_ * N_];
__device__ __align__(16) float g_R1t[(size_t)B_ * TO_ * N_];
__device__ __align__(16) float g_Dt [(size_t)B_ * TO_ * N_];
__device__ float g_lam[B_];

// ---------------- PTX helpers ----------------
__device__ __forceinline__ uint32_t smem_u32(const void* p) {
    uint32_t a;
    asm("{ .reg .u64 t; cvta.to.shared.u64 t, %1; cvt.u32.u64 %0, t; }" : "=r"(a) : "l"(p));
    return a;
}
#define CP16(dst, src) asm volatile("cp.async.cg.shared.global [%0], [%1], 16;" :: "r"(dst), "l"(src))
#define CP_COMMIT() asm volatile("cp.async.commit_group;" ::: "memory")
#define CP_WAIT(n)  asm volatile("cp.async.wait_group %0;" :: "n"(n) : "memory")

__device__ __forceinline__ void ldsm4(unsigned* r, uint32_t addr) {
    asm volatile("ldmatrix.sync.aligned.m8n8.x4.shared.b16 {%0,%1,%2,%3}, [%4];"
                 : "=r"(r[0]), "=r"(r[1]), "=r"(r[2]), "=r"(r[3]) : "r"(addr));
}
__device__ __forceinline__ void mma16816(float* c, const unsigned* a, const unsigned* b) {
    asm volatile("mma.sync.aligned.m16n8k16.row.col.f32.bf16.bf16.f32 "
                 "{%0,%1,%2,%3}, {%4,%5,%6,%7}, {%8,%9}, {%0,%1,%2,%3};"
                 : "+f"(c[0]), "+f"(c[1]), "+f"(c[2]), "+f"(c[3])
                 : "r"(a[0]), "r"(a[1]), "r"(a[2]), "r"(a[3]), "r"(b[0]), "r"(b[1]));
}
__device__ __forceinline__ void split_bf16x4(float4 v, uint2& h, uint2& l) {
    __nv_bfloat16 h0 = __float2bfloat16(v.x), h1 = __float2bfloat16(v.y);
    __nv_bfloat16 h2 = __float2bfloat16(v.z), h3 = __float2bfloat16(v.w);
    __nv_bfloat16 l0 = __float2bfloat16(v.x - __bfloat162float(h0));
    __nv_bfloat16 l1 = __float2bfloat16(v.y - __bfloat162float(h1));
    __nv_bfloat16 l2 = __float2bfloat16(v.z - __bfloat162float(h2));
    __nv_bfloat16 l3 = __float2bfloat16(v.w - __bfloat162float(h3));
    h.x = ((unsigned)__bfloat16_as_ushort(h1) << 16) | __bfloat16_as_ushort(h0);
    h.y = ((unsigned)__bfloat16_as_ushort(h3) << 16) | __bfloat16_as_ushort(h2);
    l.x = ((unsigned)__bfloat16_as_ushort(l1) << 16) | __bfloat16_as_ushort(l0);
    l.y = ((unsigned)__bfloat16_as_ushort(l3) << 16) | __bfloat16_as_ushort(l2);
}

// ---------------- lambda init + rowsum + A split ----------------
__global__ void lam_init_kernel() {
    if (threadIdx.x < B_) g_lam[threadIdx.x] = 1.0f;
}

__global__ __launch_bounds__(256) void rowsum_conv_kernel(const float* __restrict__ A) {
    __shared__ float red[8];
    int row = blockIdx.x;
    int b = row >> 10;
    int t = threadIdx.x;
    const float4* ap = (const float4*)(A + (size_t)row * N_);
    float4 v = ap[t];
    uint2 h, l;
    split_bf16x4(v, h, l);
    ((uint2*)g_Ah)[(size_t)row * 256 + t] = h;
    ((uint2*)g_Al)[(size_t)row * 256 + t] = l;

    float s = v.x + v.y + v.z + v.w;
#pragma unroll
    for (int off = 16; off > 0; off >>= 1) s += __shfl_xor_sync(0xFFFFFFFF, s, off);
    if ((t & 31) == 0) red[t >> 5] = s;
    __syncthreads();
    if (t < 8) {
        float ss = red[t];
#pragma unroll
        for (int off = 4; off > 0; off >>= 1) ss += __shfl_xor_sync(0xFF, ss, off);
        if (t == 0) atomicMax((int*)&g_lam[b], __float_as_int(ss));
    }
}

// ---------------- feat on HMMA: out[row, c] = x[row,:64] @ W[:64, c], c in 0..191 ----------------
// c = k*64 + o; k=0 -> D (fp32), k=1 -> R1 (fp32), k=2 -> R2 (bf16 split); all [b][t*64+o][n]
#define F_WH  0
#define F_WL  24576
#define F_XH  49152
#define F_XL  65536
#define F_RA  81920
#define FEAT_SMEM (81920 + 50688)

__global__ __launch_bounds__(256) void feat_mma(const float* __restrict__ x,
                                                const float* __restrict__ Th) {
    extern __shared__ __align__(1024) char fs[];
    uint32_t sb = smem_u32(fs);
    int tid = threadIdx.x, lane = tid & 31, wid = tid >> 5;
    int wr = wid & 3, wh = wid >> 2;

    // ---- W staging + split/transpose (once per block) ----
    float* sWf = (float*)(fs + F_RA);   // [64][196]
    for (int i = tid; i < 64 * 192; i += 256) {
        int f = i / 192, c = i % 192;
        int k = c >> 6, o = c & 63;
        float v;
        if (k == 0) v = Th[f * 64 + o] - Th[2 * 4096 + f * 64 + o];
        else        v = Th[k * 4096 + f * 64 + o];
        sWf[f * 196 + c] = v;
    }
    __syncthreads();
    for (int task = tid; task < 1536; task += 256) {  // 192 rows(c) x 8 chunks(f8)
        int c = task >> 3, ch = task & 7;
        float4 v0, v1;
        v0.x = sWf[(ch * 8 + 0) * 196 + c]; v0.y = sWf[(ch * 8 + 1) * 196 + c];
        v0.z = sWf[(ch * 8 + 2) * 196 + c]; v0.w = sWf[(ch * 8 + 3) * 196 + c];
        v1.x = sWf[(ch * 8 + 4) * 196 + c]; v1.y = sWf[(ch * 8 + 5) * 196 + c];
        v1.z = sWf[(ch * 8 + 6) * 196 + c]; v1.w = sWf[(ch * 8 + 7) * 196 + c];
        uint2 h0, l0, h1, l1;
        split_bf16x4(v0, h0, l0);
        split_bf16x4(v1, h1, l1);
        uint32_t addr = (uint32_t)(c * 128 + ((ch ^ (c & 7)) << 4));
        *(uint4*)(fs + F_WH + addr) = make_uint4(h0.x, h0.y, h1.x, h1.y);
        *(uint4*)(fs + F_WL + addr) = make_uint4(l0.x, l0.y, l1.x, l1.y);
    }

    int a_r = (lane & 7) + ((lane >> 3) & 1) * 8;
    int a_c = lane >> 4;
    int b_r = (lane & 7) + (lane >> 4) * 8;
    int b_c = (lane >> 3) & 1;
    int rr = lane >> 2, cc = (lane & 3) * 2;

    for (int tile = 0; tile < 4; tile++) {
        int rows_base = blockIdx.x * 512 + tile * 128;
        __syncthreads();   // protect xh/xl and region A reuse
        // ---- x load + split ----
        for (int task = tid; task < 1024; task += 256) {  // 128 rows x 8 chunks
            int r = task >> 3, ch = task & 7;
            const float4* px = (const float4*)(x + (size_t)(rows_base + r) * 64 + ch * 8);
            float4 v0 = px[0], v1 = px[1];
            uint2 h0, l0, h1, l1;
            split_bf16x4(v0, h0, l0);
            split_bf16x4(v1, h1, l1);
            uint32_t addr = (uint32_t)(r * 128 + ((ch ^ (r & 7)) << 4));
            *(uint4*)(fs + F_XH + addr) = make_uint4(h0.x, h0.y, h1.x, h1.y);
            *(uint4*)(fs + F_XL + addr) = make_uint4(l0.x, l0.y, l1.x, l1.y);
        }
        __syncthreads();

        // ---- MMA: warp = rows [wr*32,+32) x cols [wh*96,+96) ----
        float acc[2][12][4];
#pragma unroll
        for (int i = 0; i < 2; i++)
#pragma unroll
            for (int j = 0; j < 12; j++)
#pragma unroll
                for (int q = 0; q < 4; q++) acc[i][j][q] = 0.f;

#pragma unroll
        for (int kk = 0; kk < 4; kk++) {
            unsigned ah[2][4], al[2][4], bh[6][4], bl[6][4];
#pragma unroll
            for (int i = 0; i < 2; i++) {
                int row = wr * 32 + 16 * i + a_r;
                int chunk = kk * 2 + a_c;
                uint32_t addr = (uint32_t)(row * 128 + ((chunk ^ (row & 7)) << 4));
                ldsm4(ah[i], sb + F_XH + addr);
                ldsm4(al[i], sb + F_XL + addr);
            }
#pragma unroll
            for (int jj = 0; jj < 6; jj++) {
                int row = wh * 96 + 16 * jj + b_r;
                int chunk = kk * 2 + b_c;
                uint32_t addr = (uint32_t)(row * 128 + ((chunk ^ (row & 7)) << 4));
                ldsm4(bh[jj], sb + F_WH + addr);
                ldsm4(bl[jj], sb + F_WL + addr);
            }
#pragma unroll
            for (int i = 0; i < 2; i++)
#pragma unroll
                for (int j = 0; j < 12; j++) {
                    const unsigned* pbh = &bh[j >> 1][(j & 1) * 2];
                    const unsigned* pbl = &bl[j >> 1][(j & 1) * 2];
                    mma16816(acc[i][j], ah[i], pbh);
                    mma16816(acc[i][j], ah[i], pbl);
                    mma16816(acc[i][j], al[i], pbh);
                }
        }

        // ---- epilogue: transpose to [to][n] and store ----
        int bt = rows_base >> 10;
        int bb = bt / T_, tt = bt % T_;
        int n0 = rows_base & 1023;
        float* sT = (float*)(fs + F_RA);   // [96][132]
        for (int half = 0; half < 2; half++) {
            __syncthreads();
            if (wh == half) {
#pragma unroll
                for (int i = 0; i < 2; i++)
#pragma unroll
                    for (int j = 0; j < 12; j++)
#pragma unroll
                        for (int h = 0; h < 2; h++) {
                            int row = wr * 32 + 16 * i + rr + 8 * h;
                            int col = 8 * j + cc;
                            sT[col * 132 + row]       = acc[i][j][2 * h + 0];
                            sT[(col + 1) * 132 + row] = acc[i][j][2 * h + 1];
                        }
            }
            __syncthreads();
            for (int task = tid; task < 1536; task += 256) {  // 96 cols x 16 n-chunks(8)
                int cl = task >> 4, ch8 = task & 15;
                int c = half * 96 + cl;
                int k = c >> 6, o = c & 63;
                const float* src = &sT[cl * 132 + ch8 * 8];
                size_t gi = ((size_t)bb * TO_ + tt * 64 + o) * N_ + n0 + ch8 * 8;
                float4 v0 = make_float4(src[0], src[1], src[2], src[3]);
                float4 v1 = make_float4(src[4], src[5], src[6], src[7]);
                if (k < 2) {
                    float* dst = (k == 0) ? g_Dt : g_R1t;
                    *(float4*)&dst[gi]     = v0;
                    *(float4*)&dst[gi + 4] = v1;
                } else {
                    uint2 h0, l0, h1, l1;
                    split_bf16x4(v0, h0, l0);
                    split_bf16x4(v1, h1, l1);
                    *(uint4*)&g_R2h[gi] = make_uint4(h0.x, h0.y, h1.x, h1.y);
                    *(uint4*)&g_R2l[gi] = make_uint4(l0.x, l0.y, l1.x, l1.y);
                }
            }
        }
    }
}

// ---------------- HMMA GEMM: C[128x128] = A[b] @ Bsrc[b], split-bf16 x3 ----------------
#define STAGE_BYTES 65536
#define GEMM_SMEM   (3 * STAGE_BYTES)

__device__ __forceinline__ void fill_stage(uint32_t st, int kt, int bm0, int bn0,
                                           const __nv_bfloat16* __restrict__ Ah,
                                           const __nv_bfloat16* __restrict__ Al,
                                           const __nv_bfloat16* __restrict__ Bh,
                                           const __nv_bfloat16* __restrict__ Bl, int tid) {
    int ch = tid & 7, r0 = tid >> 3;
#pragma unroll
    for (int i = 0; i < 4; i++) {
        int row = r0 + 32 * i;
        uint32_t sw = (uint32_t)(row * 128 + ((ch ^ (row & 7)) << 4));
        size_t ao = (size_t)(bm0 + row) * N_ + kt + ch * 8;
        size_t bo = (size_t)(bn0 + row) * N_ + kt + ch * 8;
        CP16(st + sw,         Ah + ao);
        CP16(st + 16384 + sw, Al + ao);
        CP16(st + 32768 + sw, Bh + bo);
        CP16(st + 49152 + sw, Bl + bo);
    }
}

template <int MODE>
__global__ __launch_bounds__(256) void gemm_hmma(float* __restrict__ out) {
    extern __shared__ __align__(1024) char smem[];
    uint32_t sb = smem_u32(smem);
    int tid = threadIdx.x, lane = tid & 31, wid = tid >> 5;
    int wm = wid & 1, wn = wid >> 1;
    int b = blockIdx.z, bm0 = blockIdx.y * 128, bn0 = blockIdx.x * 128;

    const __nv_bfloat16* Agh = g_Ah + ((size_t)b << 20);
    const __nv_bfloat16* Agl = g_Al + ((size_t)b << 20);
    const __nv_bfloat16* Bgh = (MODE == 1) ? (g_R2h + (size_t)b * TO_ * N_) : (g_Zh + (size_t)b * TO_ * N_);
    const __nv_bfloat16* Bgl = (MODE == 1) ? (g_R2l + (size_t)b * TO_ * N_) : (g_Zl + (size_t)b * TO_ * N_);

    float acc[4][4][4];
#pragma unroll
    for (int i = 0; i < 4; i++)
#pragma unroll
        for (int j = 0; j < 4; j++)
#pragma unroll
            for (int q = 0; q < 4; q++) acc[i][j][q] = 0.f;

    int a_r = (lane & 7) + ((lane >> 3) & 1) * 8;
    int a_c = lane >> 4;
    int b_r = (lane & 7) + (lane >> 4) * 8;
    int b_c = (lane >> 3) & 1;

    // precomputed row components
    int rowA[4], rowB[2];
#pragma unroll
    for (int i = 0; i < 4; i++) rowA[i] = wm * 64 + 16 * i + a_r;
#pragma unroll
    for (int j2 = 0; j2 < 2; j2++) rowB[j2] = wn * 32 + 16 * j2 + b_r;

    unsigned ah[2][4][4], al[2][4][4], bh[2][2][4], bl[2][2][4];

#pragma unroll
    for (int c = 0; c < 3; c++) {
        fill_stage(sb + c * STAGE_BYTES, c * 64, bm0, bn0, Agh, Agl, Bgh, Bgl, tid);
        CP_COMMIT();
    }

#define LOAD_FRAGS(BUF, STG, KK) do {                                              \
        _Pragma("unroll")                                                          \
        for (int i = 0; i < 4; i++) {                                              \
            uint32_t ad = (STG) + (uint32_t)(rowA[i] * 128 +                       \
                ((((KK) * 2 + a_c) ^ (rowA[i] & 7)) << 4));                        \
            ldsm4(ah[BUF][i], ad);                                                 \
            ldsm4(al[BUF][i], ad + 16384);                                         \
        }                                                                          \
        _Pragma("unroll")                                                          \
        for (int j2 = 0; j2 < 2; j2++) {                                           \
            uint32_t bd = (STG) + 32768 + (uint32_t)(rowB[j2] * 128 +              \
                ((((KK) * 2 + b_c) ^ (rowB[j2] & 7)) << 4));                       \
            ldsm4(bh[BUF][j2], bd);                                                \
            ldsm4(bl[BUF][j2], bd + 16384);                                        \
        }                                                                          \
    } while (0)

    for (int c = 0; c < 16; c++) {
        uint32_t stage = sb + (c % 3) * STAGE_BYTES;
        if (c <= 13)      CP_WAIT(2);
        else if (c == 14) CP_WAIT(1);
        else              CP_WAIT(0);
        __syncthreads();

        LOAD_FRAGS(0, stage, 0);
#pragma unroll
        for (int kk = 0; kk < 4; kk++) {
            int cur = kk & 1;
            if (kk < 3) {
                if (cur) LOAD_FRAGS(0, stage, kk + 1);
                else     LOAD_FRAGS(1, stage, kk + 1);
            }
#pragma unroll
            for (int i = 0; i < 4; i++)
#pragma unroll
                for (int j = 0; j < 4; j++) {
                    const unsigned* pbh = &bh[cur][j >> 1][(j & 1) * 2];
                    const unsigned* pbl = &bl[cur][j >> 1][(j & 1) * 2];
                    mma16816(acc[i][j], ah[cur][i], pbh);
                    mma16816(acc[i][j], ah[cur][i], pbl);
                    mma16816(acc[i][j], al[cur][i], pbh);
                }
        }

        if (c + 3 < 16) {
            __syncthreads();
            fill_stage(stage, (c + 3) * 64, bm0, bn0, Agh, Agl, Bgh, Bgl, tid);
            CP_COMMIT();
        }
    }

    // ---------------- epilogue ----------------
    float lam = g_lam[b];
    int m0 = bm0 + wm * 64, to0 = bn0 + wn * 32;
    int rr = lane >> 2, cc = (lane & 3) * 2;

    if (MODE == 1) {
        float s4 = 4.0f / lam;
#pragma unroll
        for (int i = 0; i < 4; i++)
#pragma unroll
            for (int j = 0; j < 4; j++)
#pragma unroll
                for (int h = 0; h < 2; h++) {
                    int n = m0 + 16 * i + rr + 8 * h;
#pragma unroll
                    for (int q = 0; q < 2; q++) {
                        int to = to0 + 8 * j + cc + q;
                        size_t bi = ((size_t)b * TO_ + to) * N_ + n;
                        float r2 = __bfloat162float(g_R2h[bi]) + __bfloat162float(g_R2l[bi]);
                        float z = g_R1t[bi] + s4 * acc[i][j][2 * h + q] - 2.0f * r2;
                        __nv_bfloat16 zh = __float2bfloat16(z);
                        g_Zh[bi] = zh;
                        g_Zl[bi] = __float2bfloat16(z - __bfloat162float(zh));
                    }
                }
    } else {
        float s2 = 2.0f / lam;
        int t = (bn0 + wn * 32) >> 6;
        int o0 = (bn0 + wn * 32) & 63;
#pragma unroll
        for (int i = 0; i < 4; i++)
#pragma unroll
            for (int j = 0; j < 4; j++)
#pragma unroll
                for (int h = 0; h < 2; h++) {
                    int n = m0 + 16 * i + rr + 8 * h;
                    float2 v;
#pragma unroll
                    for (int q = 0; q < 2; q++) {
                        int to = to0 + 8 * j + cc + q;
                        size_t bi = ((size_t)b * TO_ + to) * N_ + n;
                        float z = __bfloat162float(g_Zh[bi]) + __bfloat162float(g_Zl[bi]);
                        float val = g_Dt[bi] + s2 * acc[i][j][2 * h + q] - z;
                        ((float*)&v)[q] = fmaxf(val, 0.f);
                    }
                    size_t oi = ((size_t)(b * T_ + t) * N_ + n) * 64 + o0 + 8 * j + cc;
                    *(float2*)&out[oi] = v;
                }
    }
}

// ---------------- launch ----------------
extern "C" void kernel_launch(void* const* d_in, const int* in_sizes, int n_in,
                              void* d_out, int out_size) {
    const float* x = nullptr;
    const float* A = nullptr;
    const float* Th = nullptr;
    for (int i = 0; i < n_in; i++) {
        if (in_sizes[i] == B_ * N_ * N_)           A  = (const float*)d_in[i];
        else if (in_sizes[i] == B_ * T_ * N_ * F_) x  = (const float*)d_in[i];
        else if (in_sizes[i] == 3 * F_ * 64)       Th = (const float*)d_in[i];
    }
    float* out = (float*)d_out;

    cudaFuncSetAttribute(gemm_hmma<1>, cudaFuncAttributeMaxDynamicSharedMemorySize, GEMM_SMEM);
    cudaFuncSetAttribute(gemm_hmma<2>, cudaFuncAttributeMaxDynamicSharedMemorySize, GEMM_SMEM);
    cudaFuncSetAttribute(feat_mma, cudaFuncAttributeMaxDynamicSharedMemorySize, FEAT_SMEM);

    lam_init_kernel<<<1, 32>>>();
    rowsum_conv_kernel<<<B_ * N_, 256>>>(A);
    feat_mma<<<(B_ * T_ * N_) / 512, 256, FEAT_SMEM>>>(x, Th);
    dim3 gg(TO_ / 128, N_ / 128, B_);
    gemm_hmma<1><<<gg, 256, GEMM_SMEM>>>(out);
    gemm_hmma<2><<<gg, 256, GEMM_SMEM>>>(out);
}

// round 7
// speedup vs baseline: 3.6142x; 1.0054x over previous
#include <cuda_runtime.h>
#include <cuda_bf16.h>
#include <cstdint>

#define B_  32
#define T_  12
#define N_  1024
#define F_  64
#define TO_ 768   // T_*O

// ---------------- device scratch (allocation-free rule) ----------------
__device__ __align__(16) __nv_bfloat16 g_Ah[(size_t)B_ * N_ * N_];
__device__ __align__(16) __nv_bfloat16 g_Al[(size_t)B_ * N_ * N_];
__device__ __align__(16) __nv_bfloat16 g_R2h[(size_t)B_ * TO_ * N_];
__device__ __align__(16) __nv_bfloat16 g_R2l[(size_t)B_ * TO_ * N_];
__device__ __align__(16) __nv_bfloat16 g_Zh[(size_t)B_ * TO_ * N_];
__device__ __align__(16) __nv_bfloat16 g_Zl[(size_t)B_ * TO_ * N_];
__device__ __align__(16) float g_R1t[(size_t)B_ * TO_ * N_];
__device__ __align__(16) float g_Dt [(size_t)B_ * TO_ * N_];
__device__ float g_lam[B_];

// ---------------- PTX helpers ----------------
__device__ __forceinline__ uint32_t smem_u32(const void* p) {
    uint32_t a;
    asm("{ .reg .u64 t; cvta.to.shared.u64 t, %1; cvt.u32.u64 %0, t; }" : "=r"(a) : "l"(p));
    return a;
}
#define CP16(dst, src) asm volatile("cp.async.cg.shared.global [%0], [%1], 16;" :: "r"(dst), "l"(src))
#define CP_COMMIT() asm volatile("cp.async.commit_group;" ::: "memory")
#define CP_WAIT(n)  asm volatile("cp.async.wait_group %0;" :: "n"(n) : "memory")

__device__ __forceinline__ void ldsm4(unsigned* r, uint32_t addr) {
    asm volatile("ldmatrix.sync.aligned.m8n8.x4.shared.b16 {%0,%1,%2,%3}, [%4];"
                 : "=r"(r[0]), "=r"(r[1]), "=r"(r[2]), "=r"(r[3]) : "r"(addr));
}
__device__ __forceinline__ void mma16816(float* c, const unsigned* a, const unsigned* b) {
    asm volatile("mma.sync.aligned.m16n8k16.row.col.f32.bf16.bf16.f32 "
                 "{%0,%1,%2,%3}, {%4,%5,%6,%7}, {%8,%9}, {%0,%1,%2,%3};"
                 : "+f"(c[0]), "+f"(c[1]), "+f"(c[2]), "+f"(c[3])
                 : "r"(a[0]), "r"(a[1]), "r"(a[2]), "r"(a[3]), "r"(b[0]), "r"(b[1]));
}
__device__ __forceinline__ void split_bf16x4(float4 v, uint2& h, uint2& l) {
    __nv_bfloat16 h0 = __float2bfloat16(v.x), h1 = __float2bfloat16(v.y);
    __nv_bfloat16 h2 = __float2bfloat16(v.z), h3 = __float2bfloat16(v.w);
    __nv_bfloat16 l0 = __float2bfloat16(v.x - __bfloat162float(h0));
    __nv_bfloat16 l1 = __float2bfloat16(v.y - __bfloat162float(h1));
    __nv_bfloat16 l2 = __float2bfloat16(v.z - __bfloat162float(h2));
    __nv_bfloat16 l3 = __float2bfloat16(v.w - __bfloat162float(h3));
    h.x = ((unsigned)__bfloat16_as_ushort(h1) << 16) | __bfloat16_as_ushort(h0);
    h.y = ((unsigned)__bfloat16_as_ushort(h3) << 16) | __bfloat16_as_ushort(h2);
    l.x = ((unsigned)__bfloat16_as_ushort(l1) << 16) | __bfloat16_as_ushort(l0);
    l.y = ((unsigned)__bfloat16_as_ushort(l3) << 16) | __bfloat16_as_ushort(l2);
}

// ---------------- lambda init + rowsum + A split ----------------
__global__ void lam_init_kernel() {
    if (threadIdx.x < B_) g_lam[threadIdx.x] = 1.0f;
}

__global__ __launch_bounds__(256) void rowsum_conv_kernel(const float* __restrict__ A) {
    __shared__ float red[8];
    int row = blockIdx.x;
    int b = row >> 10;
    int t = threadIdx.x;
    const float4* ap = (const float4*)(A + (size_t)row * N_);
    float4 v = ap[t];
    uint2 h, l;
    split_bf16x4(v, h, l);
    ((uint2*)g_Ah)[(size_t)row * 256 + t] = h;
    ((uint2*)g_Al)[(size_t)row * 256 + t] = l;

    float s = v.x + v.y + v.z + v.w;
#pragma unroll
    for (int off = 16; off > 0; off >>= 1) s += __shfl_xor_sync(0xFFFFFFFF, s, off);
    if ((t & 31) == 0) red[t >> 5] = s;
    __syncthreads();
    if (t < 8) {
        float ss = red[t];
#pragma unroll
        for (int off = 4; off > 0; off >>= 1) ss += __shfl_xor_sync(0xFF, ss, off);
        if (t == 0) atomicMax((int*)&g_lam[b], __float_as_int(ss));
    }
}

// ---------------- feat on HMMA: out[row, c] = x[row,:64] @ W[:64, c], c in 0..191 ----------------
#define F_WH  0
#define F_WL  24576
#define F_XH  49152
#define F_XL  65536
#define F_RA  81920
#define FEAT_SMEM (81920 + 50688)

__global__ __launch_bounds__(256) void feat_mma(const float* __restrict__ x,
                                                const float* __restrict__ Th) {
    extern __shared__ __align__(1024) char fs[];
    uint32_t sb = smem_u32(fs);
    int tid = threadIdx.x, lane = tid & 31, wid = tid >> 5;
    int wr = wid & 3, wh = wid >> 2;

    // ---- W staging + split/transpose (once per block) ----
    float* sWf = (float*)(fs + F_RA);   // [64][196]
    for (int i = tid; i < 64 * 192; i += 256) {
        int f = i / 192, c = i % 192;
        int k = c >> 6, o = c & 63;
        float v;
        if (k == 0) v = Th[f * 64 + o] - Th[2 * 4096 + f * 64 + o];
        else        v = Th[k * 4096 + f * 64 + o];
        sWf[f * 196 + c] = v;
    }
    __syncthreads();
    for (int task = tid; task < 1536; task += 256) {
        int c = task >> 3, ch = task & 7;
        float4 v0, v1;
        v0.x = sWf[(ch * 8 + 0) * 196 + c]; v0.y = sWf[(ch * 8 + 1) * 196 + c];
        v0.z = sWf[(ch * 8 + 2) * 196 + c]; v0.w = sWf[(ch * 8 + 3) * 196 + c];
        v1.x = sWf[(ch * 8 + 4) * 196 + c]; v1.y = sWf[(ch * 8 + 5) * 196 + c];
        v1.z = sWf[(ch * 8 + 6) * 196 + c]; v1.w = sWf[(ch * 8 + 7) * 196 + c];
        uint2 h0, l0, h1, l1;
        split_bf16x4(v0, h0, l0);
        split_bf16x4(v1, h1, l1);
        uint32_t addr = (uint32_t)(c * 128 + ((ch ^ (c & 7)) << 4));
        *(uint4*)(fs + F_WH + addr) = make_uint4(h0.x, h0.y, h1.x, h1.y);
        *(uint4*)(fs + F_WL + addr) = make_uint4(l0.x, l0.y, l1.x, l1.y);
    }

    int a_r = (lane & 7) + ((lane >> 3) & 1) * 8;
    int a_c = lane >> 4;
    int b_r = (lane & 7) + (lane >> 4) * 8;
    int b_c = (lane >> 3) & 1;
    int rr = lane >> 2, cc = (lane & 3) * 2;

    for (int tile = 0; tile < 4; tile++) {
        int rows_base = blockIdx.x * 512 + tile * 128;
        __syncthreads();
        for (int task = tid; task < 1024; task += 256) {
            int r = task >> 3, ch = task & 7;
            const float4* px = (const float4*)(x + (size_t)(rows_base + r) * 64 + ch * 8);
            float4 v0 = px[0], v1 = px[1];
            uint2 h0, l0, h1, l1;
            split_bf16x4(v0, h0, l0);
            split_bf16x4(v1, h1, l1);
            uint32_t addr = (uint32_t)(r * 128 + ((ch ^ (r & 7)) << 4));
            *(uint4*)(fs + F_XH + addr) = make_uint4(h0.x, h0.y, h1.x, h1.y);
            *(uint4*)(fs + F_XL + addr) = make_uint4(l0.x, l0.y, l1.x, l1.y);
        }
        __syncthreads();

        float acc[2][12][4];
#pragma unroll
        for (int i = 0; i < 2; i++)
#pragma unroll
            for (int j = 0; j < 12; j++)
#pragma unroll
                for (int q = 0; q < 4; q++) acc[i][j][q] = 0.f;

#pragma unroll
        for (int kk = 0; kk < 4; kk++) {
            unsigned ah[2][4], al[2][4], bh[6][4], bl[6][4];
#pragma unroll
            for (int i = 0; i < 2; i++) {
                int row = wr * 32 + 16 * i + a_r;
                int chunk = kk * 2 + a_c;
                uint32_t addr = (uint32_t)(row * 128 + ((chunk ^ (row & 7)) << 4));
                ldsm4(ah[i], sb + F_XH + addr);
                ldsm4(al[i], sb + F_XL + addr);
            }
#pragma unroll
            for (int jj = 0; jj < 6; jj++) {
                int row = wh * 96 + 16 * jj + b_r;
                int chunk = kk * 2 + b_c;
                uint32_t addr = (uint32_t)(row * 128 + ((chunk ^ (row & 7)) << 4));
                ldsm4(bh[jj], sb + F_WH + addr);
                ldsm4(bl[jj], sb + F_WL + addr);
            }
            // product-major order: same-acc reuse distance = 24 MMAs
#pragma unroll
            for (int p = 0; p < 3; p++)
#pragma unroll
                for (int i = 0; i < 2; i++)
#pragma unroll
                    for (int j = 0; j < 12; j++) {
                        const unsigned* pa = (p < 2) ? ah[i] : al[i];
                        const unsigned* pb = (p == 1) ? &bl[j >> 1][(j & 1) * 2]
                                                      : &bh[j >> 1][(j & 1) * 2];
                        mma16816(acc[i][j], pa, pb);
                    }
        }

        // ---- epilogue: transpose to [to][n] and store ----
        int bt = rows_base >> 10;
        int bb = bt / T_, tt = bt % T_;
        int n0 = rows_base & 1023;
        float* sT = (float*)(fs + F_RA);   // [96][132]
        for (int half = 0; half < 2; half++) {
            __syncthreads();
            if (wh == half) {
#pragma unroll
                for (int i = 0; i < 2; i++)
#pragma unroll
                    for (int j = 0; j < 12; j++)
#pragma unroll
                        for (int h = 0; h < 2; h++) {
                            int row = wr * 32 + 16 * i + rr + 8 * h;
                            int col = 8 * j + cc;
                            sT[col * 132 + row]       = acc[i][j][2 * h + 0];
                            sT[(col + 1) * 132 + row] = acc[i][j][2 * h + 1];
                        }
            }
            __syncthreads();
            for (int task = tid; task < 1536; task += 256) {
                int cl = task >> 4, ch8 = task & 15;
                int c = half * 96 + cl;
                int k = c >> 6, o = c & 63;
                const float* src = &sT[cl * 132 + ch8 * 8];
                size_t gi = ((size_t)bb * TO_ + tt * 64 + o) * N_ + n0 + ch8 * 8;
                float4 v0 = make_float4(src[0], src[1], src[2], src[3]);
                float4 v1 = make_float4(src[4], src[5], src[6], src[7]);
                if (k < 2) {
                    float* dst = (k == 0) ? g_Dt : g_R1t;
                    *(float4*)&dst[gi]     = v0;
                    *(float4*)&dst[gi + 4] = v1;
                } else {
                    uint2 h0, l0, h1, l1;
                    split_bf16x4(v0, h0, l0);
                    split_bf16x4(v1, h1, l1);
                    *(uint4*)&g_R2h[gi] = make_uint4(h0.x, h0.y, h1.x, h1.y);
                    *(uint4*)&g_R2l[gi] = make_uint4(l0.x, l0.y, l1.x, l1.y);
                }
            }
        }
    }
}

// ---------------- HMMA GEMM: C[128x128] = A[b] @ Bsrc[b], split-bf16 x3 ----------------
#define STAGE_BYTES 65536
#define GEMM_SMEM   (3 * STAGE_BYTES)

__device__ __forceinline__ void fill_stage(uint32_t st, int kt, int bm0, int bn0,
                                           const __nv_bfloat16* __restrict__ Ah,
                                           const __nv_bfloat16* __restrict__ Al,
                                           const __nv_bfloat16* __restrict__ Bh,
                                           const __nv_bfloat16* __restrict__ Bl, int tid) {
    int ch = tid & 7, r0 = tid >> 3;
#pragma unroll
    for (int i = 0; i < 4; i++) {
        int row = r0 + 32 * i;
        uint32_t sw = (uint32_t)(row * 128 + ((ch ^ (row & 7)) << 4));
        size_t ao = (size_t)(bm0 + row) * N_ + kt + ch * 8;
        size_t bo = (size_t)(bn0 + row) * N_ + kt + ch * 8;
        CP16(st + sw,         Ah + ao);
        CP16(st + 16384 + sw, Al + ao);
        CP16(st + 32768 + sw, Bh + bo);
        CP16(st + 49152 + sw, Bl + bo);
    }
}

template <int MODE>
__global__ __launch_bounds__(256) void gemm_hmma(float* __restrict__ out) {
    extern __shared__ __align__(1024) char smem[];
    uint32_t sb = smem_u32(smem);
    int tid = threadIdx.x, lane = tid & 31, wid = tid >> 5;
    int wm = wid & 1, wn = wid >> 1;
    int b = blockIdx.z, bm0 = blockIdx.y * 128, bn0 = blockIdx.x * 128;

    const __nv_bfloat16* Agh = g_Ah + ((size_t)b << 20);
    const __nv_bfloat16* Agl = g_Al + ((size_t)b << 20);
    const __nv_bfloat16* Bgh = (MODE == 1) ? (g_R2h + (size_t)b * TO_ * N_) : (g_Zh + (size_t)b * TO_ * N_);
    const __nv_bfloat16* Bgl = (MODE == 1) ? (g_R2l + (size_t)b * TO_ * N_) : (g_Zl + (size_t)b * TO_ * N_);

    float acc[4][4][4];
#pragma unroll
    for (int i = 0; i < 4; i++)
#pragma unroll
        for (int j = 0; j < 4; j++)
#pragma unroll
            for (int q = 0; q < 4; q++) acc[i][j][q] = 0.f;

    int a_r = (lane & 7) + ((lane >> 3) & 1) * 8;
    int a_c = lane >> 4;
    int b_r = (lane & 7) + (lane >> 4) * 8;
    int b_c = (lane >> 3) & 1;

    int rowA[4], rowB[2];
#pragma unroll
    for (int i = 0; i < 4; i++) rowA[i] = wm * 64 + 16 * i + a_r;
#pragma unroll
    for (int j2 = 0; j2 < 2; j2++) rowB[j2] = wn * 32 + 16 * j2 + b_r;

#pragma unroll
    for (int c = 0; c < 3; c++) {
        fill_stage(sb + c * STAGE_BYTES, c * 64, bm0, bn0, Agh, Agl, Bgh, Bgl, tid);
        CP_COMMIT();
    }

    for (int c = 0; c < 16; c++) {
        uint32_t stage = sb + (c % 3) * STAGE_BYTES;
        if (c <= 13)      CP_WAIT(2);
        else if (c == 14) CP_WAIT(1);
        else              CP_WAIT(0);
        __syncthreads();

#pragma unroll
        for (int kk = 0; kk < 4; kk++) {
            unsigned ah[4][4], al[4][4], bh[2][4], bl[2][4];
#pragma unroll
            for (int i = 0; i < 4; i++) {
                uint32_t ad = stage + (uint32_t)(rowA[i] * 128 +
                    (((kk * 2 + a_c) ^ (rowA[i] & 7)) << 4));
                ldsm4(ah[i], ad);
                ldsm4(al[i], ad + 16384);
            }
#pragma unroll
            for (int j2 = 0; j2 < 2; j2++) {
                uint32_t bd = stage + 32768 + (uint32_t)(rowB[j2] * 128 +
                    (((kk * 2 + b_c) ^ (rowB[j2] & 7)) << 4));
                ldsm4(bh[j2], bd);
                ldsm4(bl[j2], bd + 16384);
            }
            // product-major order: same-acc reuse distance = 16 MMAs
#pragma unroll
            for (int p = 0; p < 3; p++)
#pragma unroll
                for (int i = 0; i < 4; i++)
#pragma unroll
                    for (int j = 0; j < 4; j++) {
                        const unsigned* pa = (p < 2) ? ah[i] : al[i];
                        const unsigned* pb = (p == 1) ? &bl[j >> 1][(j & 1) * 2]
                                                      : &bh[j >> 1][(j & 1) * 2];
                        mma16816(acc[i][j], pa, pb);
                    }
        }

        if (c + 3 < 16) {
            __syncthreads();
            fill_stage(stage, (c + 3) * 64, bm0, bn0, Agh, Agl, Bgh, Bgl, tid);
            CP_COMMIT();
        }
    }

    // ---------------- epilogue ----------------
    float lam = g_lam[b];
    int m0 = bm0 + wm * 64, to0 = bn0 + wn * 32;
    int rr = lane >> 2, cc = (lane & 3) * 2;

    if (MODE == 1) {
        float s4 = 4.0f / lam;
#pragma unroll
        for (int i = 0; i < 4; i++)
#pragma unroll
            for (int j = 0; j < 4; j++)
#pragma unroll
                for (int h = 0; h < 2; h++) {
                    int n = m0 + 16 * i + rr + 8 * h;
#pragma unroll
                    for (int q = 0; q < 2; q++) {
                        int to = to0 + 8 * j + cc + q;
                        size_t bi = ((size_t)b * TO_ + to) * N_ + n;
                        float r2 = __bfloat162float(g_R2h[bi]) + __bfloat162float(g_R2l[bi]);
                        float z = g_R1t[bi] + s4 * acc[i][j][2 * h + q] - 2.0f * r2;
                        __nv_bfloat16 zh = __float2bfloat16(z);
                        g_Zh[bi] = zh;
                        g_Zl[bi] = __float2bfloat16(z - __bfloat162float(zh));
                    }
                }
    } else {
        float s2 = 2.0f / lam;
        int t = (bn0 + wn * 32) >> 6;
        int o0 = (bn0 + wn * 32) & 63;
#pragma unroll
        for (int i = 0; i < 4; i++)
#pragma unroll
            for (int j = 0; j < 4; j++)
#pragma unroll
                for (int h = 0; h < 2; h++) {
                    int n = m0 + 16 * i + rr + 8 * h;
                    float2 v;
#pragma unroll
                    for (int q = 0; q < 2; q++) {
                        int to = to0 + 8 * j + cc + q;
                        size_t bi = ((size_t)b * TO_ + to) * N_ + n;
                        float z = __bfloat162float(g_Zh[bi]) + __bfloat162float(g_Zl[bi]);
                        float val = g_Dt[bi] + s2 * acc[i][j][2 * h + q] - z;
                        ((float*)&v)[q] = fmaxf(val, 0.f);
                    }
                    size_t oi = ((size_t)(b * T_ + t) * N_ + n) * 64 + o0 + 8 * j + cc;
                    *(float2*)&out[oi] = v;
                }
    }
}

// ---------------- launch ----------------
extern "C" void kernel_launch(void* const* d_in, const int* in_sizes, int n_in,
                              void* d_out, int out_size) {
    const float* x = nullptr;
    const float* A = nullptr;
    const float* Th = nullptr;
    for (int i = 0; i < n_in; i++) {
        if (in_sizes[i] == B_ * N_ * N_)           A  = (const float*)d_in[i];
        else if (in_sizes[i] == B_ * T_ * N_ * F_) x  = (const float*)d_in[i];
        else if (in_sizes[i] == 3 * F_ * 64)       Th = (const float*)d_in[i];
    }
    float* out = (float*)d_out;

    cudaFuncSetAttribute(gemm_hmma<1>, cudaFuncAttributeMaxDynamicSharedMemorySize, GEMM_SMEM);
    cudaFuncSetAttribute(gemm_hmma<2>, cudaFuncAttributeMaxDynamicSharedMemorySize, GEMM_SMEM);
    cudaFuncSetAttribute(feat_mma, cudaFuncAttributeMaxDynamicSharedMemorySize, FEAT_SMEM);

    lam_init_kernel<<<1, 32>>>();
    rowsum_conv_kernel<<<B_ * N_, 256>>>(A);
    feat_mma<<<(B_ * T_ * N_) / 512, 256, FEAT_SMEM>>>(x, Th);
    dim3 gg(TO_ / 128, N_ / 128, B_);
    gemm_hmma<1><<<gg, 256, GEMM_SMEM>>>(out);
    gemm_hmma<2><<<gg, 256, GEMM_SMEM>>>(out);
}

// round 11
// speedup vs baseline: 3.9172x; 1.0838x over previous
#include <cuda_runtime.h>
#include <cuda_bf16.h>
#include <cstdint>

#define B_  32
#define T_  12
#define N_  1024
#define F_  64
#define TO_ 768   // T_*O

// ---------------- device scratch (allocation-free rule) ----------------
__device__ __align__(16) __nv_bfloat16 g_Ah[(size_t)B_ * N_ * N_];
__device__ __align__(16) __nv_bfloat16 g_Al[(size_t)B_ * N_ * N_];
__device__ __align__(16) __nv_bfloat16 g_R2h[(size_t)B_ * TO_ * N_];
__device__ __align__(16) __nv_bfloat16 g_R2l[(size_t)B_ * TO_ * N_];
__device__ __align__(16) __nv_bfloat16 g_Zh[(size_t)B_ * TO_ * N_];
__device__ __align__(16) __nv_bfloat16 g_Zl[(size_t)B_ * TO_ * N_];
__device__ __align__(16) float g_R1t[(size_t)B_ * TO_ * N_];
__device__ __align__(16) float g_Dt [(size_t)B_ * TO_ * N_];
__device__ float g_lam[B_];

// ---------------- PTX helpers ----------------
__device__ __forceinline__ uint32_t smem_u32(const void* p) {
    uint32_t a;
    asm("{ .reg .u64 t; cvta.to.shared.u64 t, %1; cvt.u32.u64 %0, t; }" : "=r"(a) : "l"(p));
    return a;
}
#define CP16(dst, src) asm volatile("cp.async.cg.shared.global [%0], [%1], 16;" :: "r"(dst), "l"(src))
#define CP_COMMIT() asm volatile("cp.async.commit_group;" ::: "memory")
#define CP_WAIT(n)  asm volatile("cp.async.wait_group %0;" :: "n"(n) : "memory")

__device__ __forceinline__ void ldsm4(unsigned* r, uint32_t addr) {
    asm volatile("ldmatrix.sync.aligned.m8n8.x4.shared.b16 {%0,%1,%2,%3}, [%4];"
                 : "=r"(r[0]), "=r"(r[1]), "=r"(r[2]), "=r"(r[3]) : "r"(addr));
}
__device__ __forceinline__ void mma16816(float* c, const unsigned* a, const unsigned* b) {
    asm volatile("mma.sync.aligned.m16n8k16.row.col.f32.bf16.bf16.f32 "
                 "{%0,%1,%2,%3}, {%4,%5,%6,%7}, {%8,%9}, {%0,%1,%2,%3};"
                 : "+f"(c[0]), "+f"(c[1]), "+f"(c[2]), "+f"(c[3])
                 : "r"(a[0]), "r"(a[1]), "r"(a[2]), "r"(a[3]), "r"(b[0]), "r"(b[1]));
}
__device__ __forceinline__ void split_bf16x4(float4 v, uint2& h, uint2& l) {
    __nv_bfloat16 h0 = __float2bfloat16(v.x), h1 = __float2bfloat16(v.y);
    __nv_bfloat16 h2 = __float2bfloat16(v.z), h3 = __float2bfloat16(v.w);
    __nv_bfloat16 l0 = __float2bfloat16(v.x - __bfloat162float(h0));
    __nv_bfloat16 l1 = __float2bfloat16(v.y - __bfloat162float(h1));
    __nv_bfloat16 l2 = __float2bfloat16(v.z - __bfloat162float(h2));
    __nv_bfloat16 l3 = __float2bfloat16(v.w - __bfloat162float(h3));
    h.x = ((unsigned)__bfloat16_as_ushort(h1) << 16) | __bfloat16_as_ushort(h0);
    h.y = ((unsigned)__bfloat16_as_ushort(h3) << 16) | __bfloat16_as_ushort(h2);
    l.x = ((unsigned)__bfloat16_as_ushort(l1) << 16) | __bfloat16_as_ushort(l0);
    l.y = ((unsigned)__bfloat16_as_ushort(l3) << 16) | __bfloat16_as_ushort(l2);
}

// ---------------- lambda init + rowsum + A split ----------------
__global__ void lam_init_kernel() {
    if (threadIdx.x < B_) g_lam[threadIdx.x] = 1.0f;
}

__global__ __launch_bounds__(256) void rowsum_conv_kernel(const float* __restrict__ A) {
    __shared__ float red[8];
    int row = blockIdx.x;
    int b = row >> 10;
    int t = threadIdx.x;
    const float4* ap = (const float4*)(A + (size_t)row * N_);
    float4 v = ap[t];
    uint2 h, l;
    split_bf16x4(v, h, l);
    ((uint2*)g_Ah)[(size_t)row * 256 + t] = h;
    ((uint2*)g_Al)[(size_t)row * 256 + t] = l;

    float s = v.x + v.y + v.z + v.w;
#pragma unroll
    for (int off = 16; off > 0; off >>= 1) s += __shfl_xor_sync(0xFFFFFFFF, s, off);
    if ((t & 31) == 0) red[t >> 5] = s;
    __syncthreads();
    if (t < 8) {
        float ss = red[t];
#pragma unroll
        for (int off = 4; off > 0; off >>= 1) ss += __shfl_xor_sync(0xFF, ss, off);
        if (t == 0) atomicMax((int*)&g_lam[b], __float_as_int(ss));
    }
}

// ---------------- feat on HMMA: out[row, c] = x[row,:64] @ W[:64, c], c in 0..191 ----------------
#define F_WH  0
#define F_WL  24576
#define F_XH  49152
#define F_XL  65536
#define F_RA  81920
#define FEAT_SMEM (81920 + 50688)

__global__ __launch_bounds__(256) void feat_mma(const float* __restrict__ x,
                                                const float* __restrict__ Th) {
    extern __shared__ __align__(1024) char fs[];
    uint32_t sb = smem_u32(fs);
    int tid = threadIdx.x, lane = tid & 31, wid = tid >> 5;
    int wr = wid & 3, wh = wid >> 2;

    // ---- W staging + split/transpose (once per block) ----
    float* sWf = (float*)(fs + F_RA);   // [64][196]
    for (int i = tid; i < 64 * 192; i += 256) {
        int f = i / 192, c = i % 192;
        int k = c >> 6, o = c & 63;
        float v;
        if (k == 0) v = Th[f * 64 + o] - Th[2 * 4096 + f * 64 + o];
        else        v = Th[k * 4096 + f * 64 + o];
        sWf[f * 196 + c] = v;
    }
    __syncthreads();
    for (int task = tid; task < 1536; task += 256) {
        int c = task >> 3, ch = task & 7;
        float4 v0, v1;
        v0.x = sWf[(ch * 8 + 0) * 196 + c]; v0.y = sWf[(ch * 8 + 1) * 196 + c];
        v0.z = sWf[(ch * 8 + 2) * 196 + c]; v0.w = sWf[(ch * 8 + 3) * 196 + c];
        v1.x = sWf[(ch * 8 + 4) * 196 + c]; v1.y = sWf[(ch * 8 + 5) * 196 + c];
        v1.z = sWf[(ch * 8 + 6) * 196 + c]; v1.w = sWf[(ch * 8 + 7) * 196 + c];
        uint2 h0, l0, h1, l1;
        split_bf16x4(v0, h0, l0);
        split_bf16x4(v1, h1, l1);
        uint32_t addr = (uint32_t)(c * 128 + ((ch ^ (c & 7)) << 4));
        *(uint4*)(fs + F_WH + addr) = make_uint4(h0.x, h0.y, h1.x, h1.y);
        *(uint4*)(fs + F_WL + addr) = make_uint4(l0.x, l0.y, l1.x, l1.y);
    }

    int a_r = (lane & 7) + ((lane >> 3) & 1) * 8;
    int a_c = lane >> 4;
    int b_r = (lane & 7) + (lane >> 4) * 8;
    int b_c = (lane >> 3) & 1;
    int rr = lane >> 2, cc = (lane & 3) * 2;

    for (int tile = 0; tile < 4; tile++) {
        int rows_base = blockIdx.x * 512 + tile * 128;
        __syncthreads();
        for (int task = tid; task < 1024; task += 256) {
            int r = task >> 3, ch = task & 7;
            const float4* px = (const float4*)(x + (size_t)(rows_base + r) * 64 + ch * 8);
            float4 v0 = px[0], v1 = px[1];
            uint2 h0, l0, h1, l1;
            split_bf16x4(v0, h0, l0);
            split_bf16x4(v1, h1, l1);
            uint32_t addr = (uint32_t)(r * 128 + ((ch ^ (r & 7)) << 4));
            *(uint4*)(fs + F_XH + addr) = make_uint4(h0.x, h0.y, h1.x, h1.y);
            *(uint4*)(fs + F_XL + addr) = make_uint4(l0.x, l0.y, l1.x, l1.y);
        }
        __syncthreads();

        float acc[2][12][4];
#pragma unroll
        for (int i = 0; i < 2; i++)
#pragma unroll
            for (int j = 0; j < 12; j++)
#pragma unroll
                for (int q = 0; q < 4; q++) acc[i][j][q] = 0.f;

#pragma unroll
        for (int kk = 0; kk < 4; kk++) {
            unsigned ah[2][4], al[2][4], bh[6][4], bl[6][4];
#pragma unroll
            for (int i = 0; i < 2; i++) {
                int row = wr * 32 + 16 * i + a_r;
                int chunk = kk * 2 + a_c;
                uint32_t addr = (uint32_t)(row * 128 + ((chunk ^ (row & 7)) << 4));
                ldsm4(ah[i], sb + F_XH + addr);
                ldsm4(al[i], sb + F_XL + addr);
            }
#pragma unroll
            for (int jj = 0; jj < 6; jj++) {
                int row = wh * 96 + 16 * jj + b_r;
                int chunk = kk * 2 + b_c;
                uint32_t addr = (uint32_t)(row * 128 + ((chunk ^ (row & 7)) << 4));
                ldsm4(bh[jj], sb + F_WH + addr);
                ldsm4(bl[jj], sb + F_WL + addr);
            }
#pragma unroll
            for (int p = 0; p < 3; p++)
#pragma unroll
                for (int i = 0; i < 2; i++)
#pragma unroll
                    for (int j = 0; j < 12; j++) {
                        const unsigned* pa = (p < 2) ? ah[i] : al[i];
                        const unsigned* pb = (p == 1) ? &bl[j >> 1][(j & 1) * 2]
                                                      : &bh[j >> 1][(j & 1) * 2];
                        mma16816(acc[i][j], pa, pb);
                    }
        }

        // ---- epilogue: transpose to [to][n] and store ----
        int bt = rows_base >> 10;
        int bb = bt / T_, tt = bt % T_;
        int n0 = rows_base & 1023;
        float* sT = (float*)(fs + F_RA);   // [96][132]
        for (int half = 0; half < 2; half++) {
            __syncthreads();
            if (wh == half) {
#pragma unroll
                for (int i = 0; i < 2; i++)
#pragma unroll
                    for (int j = 0; j < 12; j++)
#pragma unroll
                        for (int h = 0; h < 2; h++) {
                            int row = wr * 32 + 16 * i + rr + 8 * h;
                            int col = 8 * j + cc;
                            sT[col * 132 + row]       = acc[i][j][2 * h + 0];
                            sT[(col + 1) * 132 + row] = acc[i][j][2 * h + 1];
                        }
            }
            __syncthreads();
            for (int task = tid; task < 1536; task += 256) {
                int cl = task >> 4, ch8 = task & 15;
                int c = half * 96 + cl;
                int k = c >> 6, o = c & 63;
                const float* src = &sT[cl * 132 + ch8 * 8];
                size_t gi = ((size_t)bb * TO_ + tt * 64 + o) * N_ + n0 + ch8 * 8;
                float4 v0 = make_float4(src[0], src[1], src[2], src[3]);
                float4 v1 = make_float4(src[4], src[5], src[6], src[7]);
                if (k < 2) {
                    float* dst = (k == 0) ? g_Dt : g_R1t;
                    *(float4*)&dst[gi]     = v0;
                    *(float4*)&dst[gi + 4] = v1;
                } else {
                    uint2 h0, l0, h1, l1;
                    split_bf16x4(v0, h0, l0);
                    split_bf16x4(v1, h1, l1);
                    *(uint4*)&g_R2h[gi] = make_uint4(h0.x, h0.y, h1.x, h1.y);
                    *(uint4*)&g_R2l[gi] = make_uint4(l0.x, l0.y, l1.x, l1.y);
                }
            }
        }
    }
}

// ---------------- HMMA GEMM: C[128x128] = A[b] @ Bsrc[b], split-bf16 x3 ----------------
// 512 threads, 4x4 warp grid, 32x32 warp tiles (occupancy-driven latency hiding)
#define STAGE_BYTES 65536
#define GEMM_SMEM   (3 * STAGE_BYTES)

__device__ __forceinline__ void fill_stage(uint32_t st, int kt, int bm0, int bn0,
                                           const __nv_bfloat16* __restrict__ Ah,
                                           const __nv_bfloat16* __restrict__ Al,
                                           const __nv_bfloat16* __restrict__ Bh,
                                           const __nv_bfloat16* __restrict__ Bl, int tid) {
    int ch = tid & 7, r0 = tid >> 3;   // r0: 0..63
#pragma unroll
    for (int i = 0; i < 2; i++) {
        int row = r0 + 64 * i;
        uint32_t sw = (uint32_t)(row * 128 + ((ch ^ (row & 7)) << 4));
        size_t ao = (size_t)(bm0 + row) * N_ + kt + ch * 8;
        size_t bo = (size_t)(bn0 + row) * N_ + kt + ch * 8;
        CP16(st + sw,         Ah + ao);
        CP16(st + 16384 + sw, Al + ao);
        CP16(st + 32768 + sw, Bh + bo);
        CP16(st + 49152 + sw, Bl + bo);
    }
}

template <int MODE>
__global__ __launch_bounds__(512) void gemm_hmma(float* __restrict__ out) {
    extern __shared__ __align__(1024) char smem[];
    uint32_t sb = smem_u32(smem);
    int tid = threadIdx.x, lane = tid & 31, wid = tid >> 5;
    int wm = wid & 3, wn = wid >> 2;     // 4x4 warps, 32x32 tiles
    int b = blockIdx.z, bm0 = blockIdx.y * 128, bn0 = blockIdx.x * 128;

    const __nv_bfloat16* Agh = g_Ah + ((size_t)b << 20);
    const __nv_bfloat16* Agl = g_Al + ((size_t)b << 20);
    const __nv_bfloat16* Bgh = (MODE == 1) ? (g_R2h + (size_t)b * TO_ * N_) : (g_Zh + (size_t)b * TO_ * N_);
    const __nv_bfloat16* Bgl = (MODE == 1) ? (g_R2l + (size_t)b * TO_ * N_) : (g_Zl + (size_t)b * TO_ * N_);

    float acc[2][4][4];
#pragma unroll
    for (int i = 0; i < 2; i++)
#pragma unroll
        for (int j = 0; j < 4; j++)
#pragma unroll
            for (int q = 0; q < 4; q++) acc[i][j][q] = 0.f;

    int a_r = (lane & 7) + ((lane >> 3) & 1) * 8;
    int a_c = lane >> 4;
    int b_r = (lane & 7) + (lane >> 4) * 8;
    int b_c = (lane >> 3) & 1;

    int rowA[2], rowB[2];
#pragma unroll
    for (int i = 0; i < 2; i++) rowA[i] = wm * 32 + 16 * i + a_r;
#pragma unroll
    for (int j2 = 0; j2 < 2; j2++) rowB[j2] = wn * 32 + 16 * j2 + b_r;

#pragma unroll
    for (int c = 0; c < 3; c++) {
        fill_stage(sb + c * STAGE_BYTES, c * 64, bm0, bn0, Agh, Agl, Bgh, Bgl, tid);
        CP_COMMIT();
    }

    for (int c = 0; c < 16; c++) {
        uint32_t stage = sb + (c % 3) * STAGE_BYTES;
        if (c <= 13)      CP_WAIT(2);
        else if (c == 14) CP_WAIT(1);
        else              CP_WAIT(0);
        __syncthreads();

#pragma unroll
        for (int kk = 0; kk < 4; kk++) {
            unsigned ah[2][4], al[2][4], bh[2][4], bl[2][4];
#pragma unroll
            for (int i = 0; i < 2; i++) {
                uint32_t ad = stage + (uint32_t)(rowA[i] * 128 +
                    (((kk * 2 + a_c) ^ (rowA[i] & 7)) << 4));
                ldsm4(ah[i], ad);
                ldsm4(al[i], ad + 16384);
            }
#pragma unroll
            for (int j2 = 0; j2 < 2; j2++) {
                uint32_t bd = stage + 32768 + (uint32_t)(rowB[j2] * 128 +
                    (((kk * 2 + b_c) ^ (rowB[j2] & 7)) << 4));
                ldsm4(bh[j2], bd);
                ldsm4(bl[j2], bd + 16384);
            }
#pragma unroll
            for (int p = 0; p < 3; p++)
#pragma unroll
                for (int i = 0; i < 2; i++)
#pragma unroll
                    for (int j = 0; j < 4; j++) {
                        const unsigned* pa = (p < 2) ? ah[i] : al[i];
                        const unsigned* pb = (p == 1) ? &bl[j >> 1][(j & 1) * 2]
                                                      : &bh[j >> 1][(j & 1) * 2];
                        mma16816(acc[i][j], pa, pb);
                    }
        }

        if (c + 3 < 16) {
            __syncthreads();
            fill_stage(stage, (c + 3) * 64, bm0, bn0, Agh, Agl, Bgh, Bgl, tid);
            CP_COMMIT();
        }
    }

    // ---------------- epilogue ----------------
    float lam = g_lam[b];
    int m0 = bm0 + wm * 32, to0 = bn0 + wn * 32;
    int rr = lane >> 2, cc = (lane & 3) * 2;

    if (MODE == 1) {
        float s4 = 4.0f / lam;
#pragma unroll
        for (int i = 0; i < 2; i++)
#pragma unroll
            for (int j = 0; j < 4; j++)
#pragma unroll
                for (int h = 0; h < 2; h++) {
                    int n = m0 + 16 * i + rr + 8 * h;
#pragma unroll
                    for (int q = 0; q < 2; q++) {
                        int to = to0 + 8 * j + cc + q;
                        size_t bi = ((size_t)b * TO_ + to) * N_ + n;
                        float r2 = __bfloat162float(g_R2h[bi]) + __bfloat162float(g_R2l[bi]);
                        float z = g_R1t[bi] + s4 * acc[i][j][2 * h + q] - 2.0f * r2;
                        __nv_bfloat16 zh = __float2bfloat16(z);
                        g_Zh[bi] = zh;
                        g_Zl[bi] = __float2bfloat16(z - __bfloat162float(zh));
                    }
                }
    } else {
        float s2 = 2.0f / lam;
        int t = (bn0 + wn * 32) >> 6;
        int o0 = (bn0 + wn * 32) & 63;
#pragma unroll
        for (int i = 0; i < 2; i++)
#pragma unroll
            for (int j = 0; j < 4; j++)
#pragma unroll
                for (int h = 0; h < 2; h++) {
                    int n = m0 + 16 * i + rr + 8 * h;
                    float2 v;
#pragma unroll
                    for (int q = 0; q < 2; q++) {
                        int to = to0 + 8 * j + cc + q;
                        size_t bi = ((size_t)b * TO_ + to) * N_ + n;
                        float z = __bfloat162float(g_Zh[bi]) + __bfloat162float(g_Zl[bi]);
                        float val = g_Dt[bi] + s2 * acc[i][j][2 * h + q] - z;
                        ((float*)&v)[q] = fmaxf(val, 0.f);
                    }
                    size_t oi = ((size_t)(b * T_ + t) * N_ + n) * 64 + o0 + 8 * j + cc;
                    *(float2*)&out[oi] = v;
                }
    }
}

// ---------------- launch ----------------
extern "C" void kernel_launch(void* const* d_in, const int* in_sizes, int n_in,
                              void* d_out, int out_size) {
    const float* x = nullptr;
    const float* A = nullptr;
    const float* Th = nullptr;
    for (int i = 0; i < n_in; i++) {
        if (in_sizes[i] == B_ * N_ * N_)           A  = (const float*)d_in[i];
        else if (in_sizes[i] == B_ * T_ * N_ * F_) x  = (const float*)d_in[i];
        else if (in_sizes[i] == 3 * F_ * 64)       Th = (const float*)d_in[i];
    }
    float* out = (float*)d_out;

    cudaFuncSetAttribute(gemm_hmma<1>, cudaFuncAttributeMaxDynamicSharedMemorySize, GEMM_SMEM);
    cudaFuncSetAttribute(gemm_hmma<2>, cudaFuncAttributeMaxDynamicSharedMemorySize, GEMM_SMEM);
    cudaFuncSetAttribute(feat_mma, cudaFuncAttributeMaxDynamicSharedMemorySize, FEAT_SMEM);

    lam_init_kernel<<<1, 32>>>();
    rowsum_conv_kernel<<<B_ * N_, 256>>>(A);
    feat_mma<<<(B_ * T_ * N_) / 512, 256, FEAT_SMEM>>>(x, Th);
    dim3 gg(TO_ / 128, N_ / 128, B_);
    gemm_hmma<1><<<gg, 512, GEMM_SMEM>>>(out);
    gemm_hmma<2><<<gg, 512, GEMM_SMEM>>>(out);
}